// round 9
// baseline (speedup 1.0000x reference)
#include <cuda_runtime.h>
#include <cuda_fp16.h>
#include <cuda_bf16.h>
#include <cstdint>

// ---------------------------------------------------------------------------
// Problem constants
// ---------------------------------------------------------------------------
#define BB    2
#define SS    1024
#define HID   4096
#define NH    64
#define NKV   8
#define HD    192
#define VD    128
#define ROT   64
#define WIN   128
#define QT    16
#define KP    161
#define SCALE 0.07216878364870323f   // 192^-0.5

#define NQ (NH * HD)     // 12288
#define NK (NKV * HD)    // 1536
#define NV (NKV * VD)    // 1024
#define NO (NH * VD)     // 8192

// ---------------------------------------------------------------------------
// Scratch (device globals; no allocations allowed)
// ---------------------------------------------------------------------------
__device__ float  g_Q [(size_t)BB * SS * NQ];     // fp32 Q (RoPE'd in place)
__device__ float  g_K [(size_t)BB * SS * NK];
__device__ float  g_V [(size_t)BB * SS * NV];
__device__ __half g_Hh [(size_t)BB * SS * HID];   // fp16 operand copies
__device__ __half g_Wqh[(size_t)HID * NQ];
__device__ __half g_Wkh[(size_t)HID * NK];
__device__ __half g_Wvh[(size_t)HID * NV];
__device__ __half g_Woh[(size_t)NO * HID];
__device__ __half g_AOh[(size_t)BB * SS * NO];    // attention output (fp16)

// ---------------------------------------------------------------------------
// Helpers
// ---------------------------------------------------------------------------
__device__ __forceinline__ uint32_t smem_u32(const void* p) {
    return (uint32_t)__cvta_generic_to_shared(p);
}

#define CP_ASYNC16(dst, src) \
    asm volatile("cp.async.cg.shared.global [%0], [%1], 16;" \
                 :: "r"(dst), "l"(src))
#define CP_COMMIT() asm volatile("cp.async.commit_group;" ::: "memory")
#define CP_WAIT2()  asm volatile("cp.async.wait_group 2;"  ::: "memory")

// ---------------------------------------------------------------------------
// fp16 mma.sync GEMM core: C(MxN fp32) = A(MxK fp16) * B(KxN fp16),
// row-major. CTA tile 128x256, K-chunk 32, 4-stage cp.async pipeline.
// 8 warps (2x4), warp tile 64x64, mma m16n8k16.
// ---------------------------------------------------------------------------
#define APITCH_B  80            // bytes per A smem row (32 fp16 + pad)
#define BPITCH_B  528           // bytes per B smem row (256 fp16 + 16B pad)
#define A_BYTES   (128 * APITCH_B)          // 10240
#define STAGE_B   (A_BYTES + 32 * BPITCH_B) // 27136
#define GEMM_SMEM (4 * STAGE_B)             // 108544

__device__ __forceinline__ void gemm_core(
    const __half* __restrict__ Ag, int lda,
    const __half* __restrict__ Bg, int ldb,
    float* __restrict__ Cg, int ldc, int Kdim)
{
    extern __shared__ char smraw[];
    const uint32_t sb0 = smem_u32(smraw);
    const int tid = threadIdx.x, lane = tid & 31, warp = tid >> 5;
    const int wm = warp & 1, wn = warp >> 1;

    // fragment smem offsets (stage-relative)
    uint32_t aoff[4], boff[4];
#pragma unroll
    for (int mt = 0; mt < 4; mt++)
        aoff[mt] = (uint32_t)(wm * 64 + mt * 16 + (lane & 15)) * APITCH_B
                 + (uint32_t)(lane >> 4) * 16;
#pragma unroll
    for (int n2 = 0; n2 < 4; n2++)
        boff[n2] = A_BYTES + (uint32_t)(lane & 15) * BPITCH_B
                 + (uint32_t)(wn * 64 + n2 * 16) * 2
                 + (uint32_t)(lane >> 4) * 16;

    float acc[4][8][4];
#pragma unroll
    for (int mt = 0; mt < 4; mt++)
#pragma unroll
        for (int nt = 0; nt < 8; nt++)
#pragma unroll
            for (int r = 0; r < 4; r++) acc[mt][nt][r] = 0.f;

    const int KT = Kdim >> 5;

    // copy issue for k-tile ktc into stage s
    const int cm = tid >> 2, ck16 = tid & 3;       // A: 2 chunks/thread
    const int cbr = tid >> 5, cbc = tid & 31;      // B: 4 chunks/thread (8 rows/pass)
#define ISSUE_COPY(ktc, s) do {                                                \
        const int _k0 = (ktc) * 32;                                            \
        const uint32_t _sa = sb0 + (s) * STAGE_B;                              \
        CP_ASYNC16(_sa + cm * APITCH_B + ck16 * 16,                            \
                   Ag + (size_t)cm * lda + _k0 + ck16 * 8);                    \
        CP_ASYNC16(_sa + (cm + 64) * APITCH_B + ck16 * 16,                     \
                   Ag + (size_t)(cm + 64) * lda + _k0 + ck16 * 8);             \
        _Pragma("unroll")                                                      \
        for (int _r = 0; _r < 4; _r++)                                         \
            CP_ASYNC16(_sa + A_BYTES + (cbr + _r * 8) * BPITCH_B + cbc * 16,   \
                       Bg + (size_t)(_k0 + cbr + _r * 8) * ldb + cbc * 8);     \
    } while (0)

#pragma unroll
    for (int p = 0; p < 3; p++) { ISSUE_COPY(p, p); CP_COMMIT(); }

    for (int kt = 0; kt < KT; kt++) {
        CP_WAIT2();
        __syncthreads();
        const uint32_t sa = sb0 + (kt & 3) * STAGE_B;

#pragma unroll
        for (int kk = 0; kk < 2; kk++) {
            uint32_t a[4][4], b[4][4];
#pragma unroll
            for (int mt = 0; mt < 4; mt++)
                asm volatile(
                    "ldmatrix.sync.aligned.m8n8.x4.shared.b16 {%0,%1,%2,%3}, [%4];"
                    : "=r"(a[mt][0]), "=r"(a[mt][1]), "=r"(a[mt][2]), "=r"(a[mt][3])
                    : "r"(sa + aoff[mt] + kk * 32));
#pragma unroll
            for (int n2 = 0; n2 < 4; n2++)
                asm volatile(
                    "ldmatrix.sync.aligned.m8n8.x4.trans.shared.b16 {%0,%1,%2,%3}, [%4];"
                    : "=r"(b[n2][0]), "=r"(b[n2][1]), "=r"(b[n2][2]), "=r"(b[n2][3])
                    : "r"(sa + boff[n2] + kk * (16 * BPITCH_B)));
#pragma unroll
            for (int mt = 0; mt < 4; mt++)
#pragma unroll
                for (int nt = 0; nt < 8; nt++)
                    asm volatile(
                        "mma.sync.aligned.m16n8k16.row.col.f32.f16.f16.f32 "
                        "{%0,%1,%2,%3}, {%4,%5,%6,%7}, {%8,%9}, {%0,%1,%2,%3};"
                        : "+f"(acc[mt][nt][0]), "+f"(acc[mt][nt][1]),
                          "+f"(acc[mt][nt][2]), "+f"(acc[mt][nt][3])
                        : "r"(a[mt][0]), "r"(a[mt][1]), "r"(a[mt][2]), "r"(a[mt][3]),
                          "r"(b[nt >> 1][(nt & 1) * 2]), "r"(b[nt >> 1][(nt & 1) * 2 + 1]));
        }

        const int ktc = kt + 3;
        if (ktc < KT) ISSUE_COPY(ktc, ktc & 3);
        CP_COMMIT();
    }
#undef ISSUE_COPY

    // epilogue
#pragma unroll
    for (int mt = 0; mt < 4; mt++) {
        const int r = wm * 64 + mt * 16 + (lane >> 2);
#pragma unroll
        for (int nt = 0; nt < 8; nt++) {
            const int cc = wn * 64 + nt * 8 + (lane & 3) * 2;
            *(float2*)&Cg[(size_t)r * ldc + cc] =
                make_float2(acc[mt][nt][0], acc[mt][nt][1]);
            *(float2*)&Cg[(size_t)(r + 8) * ldc + cc] =
                make_float2(acc[mt][nt][2], acc[mt][nt][3]);
        }
    }
}

// fused QKV projection: one grid over the concatenated N = 12288|1536|1024
__global__ __launch_bounds__(256, 1) void gemm_qkv(
    const __half* __restrict__ Hh,
    const __half* __restrict__ Wqh, const __half* __restrict__ Wkh,
    const __half* __restrict__ Wvh,
    float* __restrict__ Q, float* __restrict__ K, float* __restrict__ V)
{
    const int col0 = blockIdx.x * 256, row0 = blockIdx.y * 128;
    const __half* Bg; float* Cg; int ld;
    if (col0 < NQ)            { Bg = Wqh + col0;             Cg = Q + col0;             ld = NQ; }
    else if (col0 < NQ + NK)  { int c = col0 - NQ;  Bg = Wkh + c; Cg = K + c; ld = NK; }
    else                      { int c = col0 - NQ - NK; Bg = Wvh + c; Cg = V + c; ld = NV; }
    gemm_core(Hh + (size_t)row0 * HID, HID, Bg, ld,
              Cg + (size_t)row0 * ld, ld, HID);
}

// generic (output projection)
__global__ __launch_bounds__(256, 1) void gemm_gen(
    const __half* __restrict__ Ah, const __half* __restrict__ Bh,
    float* __restrict__ C, int lda, int ldb, int Kdim)
{
    const int col0 = blockIdx.x * 256, row0 = blockIdx.y * 128;
    gemm_core(Ah + (size_t)row0 * lda, lda, Bh + col0, ldb,
              C + (size_t)row0 * ldb + col0, ldb, Kdim);
}

// ---------------------------------------------------------------------------
// fp32 -> fp16 (rn) conversion, 16 elems/thread, exact grids
// ---------------------------------------------------------------------------
__global__ __launch_bounds__(256) void f32_to_f16(
    const float* __restrict__ in, __half* __restrict__ out)
{
    const size_t i = ((size_t)blockIdx.x * 256 + threadIdx.x) * 16;
    float4 a = *(const float4*)(in + i);
    float4 b = *(const float4*)(in + i + 4);
    float4 c = *(const float4*)(in + i + 8);
    float4 d = *(const float4*)(in + i + 12);
    union { __half2 h[4]; uint4 u; } cv0, cv1;
    cv0.h[0] = __floats2half2_rn(a.x, a.y);
    cv0.h[1] = __floats2half2_rn(a.z, a.w);
    cv0.h[2] = __floats2half2_rn(b.x, b.y);
    cv0.h[3] = __floats2half2_rn(b.z, b.w);
    cv1.h[0] = __floats2half2_rn(c.x, c.y);
    cv1.h[1] = __floats2half2_rn(c.z, c.w);
    cv1.h[2] = __floats2half2_rn(d.x, d.y);
    cv1.h[3] = __floats2half2_rn(d.z, d.w);
    *(uint4*)(out + i)     = cv0.u;
    *(uint4*)(out + i + 8) = cv1.u;
}

// ---------------------------------------------------------------------------
// Partial RoPE (rotate-half on first 64 dims), in place (fp32).
// ---------------------------------------------------------------------------
__global__ __launch_bounds__(256) void rope_kernel(
    float* __restrict__ X, const float* __restrict__ cosp,
    const float* __restrict__ sinp, int nheads)
{
    int idx = blockIdx.x * blockDim.x + threadIdx.x;
    int d  = idx & 31;
    int h  = (idx >> 5) % nheads;
    int bs = idx / (32 * nheads);

    float* base = X + ((size_t)bs * nheads + h) * HD;
    float c = cosp[bs * ROT + d];
    float s = sinp[bs * ROT + d];
    float x1 = base[d], x2 = base[d + 32];
    base[d]      = x1 * c - x2 * s;
    base[d + 32] = x2 * c + x1 * s;
}

// ---------------------------------------------------------------------------
// Sliding-window attention with sink. Output written as fp16 (GEMM operand).
// ---------------------------------------------------------------------------
__global__ __launch_bounds__(256) void attn_kernel(
    const float* __restrict__ Q, const float* __restrict__ K,
    const float* __restrict__ V, const float* __restrict__ sinks,
    __half* __restrict__ O)
{
    extern __shared__ float smn[];
    float* ks    = smn;                    // [HD][KP]
    float* vs    = smn + HD * KP;          // [144][VD]
    float* probs = vs + 144 * VD;          // [8][160]

    const int qt = blockIdx.x, kh = blockIdx.y, b = blockIdx.z;
    const int qs0 = qt * QT;
    const int jn0 = max(0, qs0 - (WIN - 1));
    const int nk  = qs0 + QT - jn0;
    const int tid = threadIdx.x;

    for (int idx = tid; idx < nk * HD; idx += 256) {
        int j = idx / HD, d = idx - j * HD;
        ks[d * KP + j] = K[(((size_t)b * SS + jn0 + j) * NKV + kh) * HD + d];
    }
    for (int idx = tid; idx < nk * VD; idx += 256) {
        int j = idx >> 7, d = idx & 127;
        vs[j * VD + d] = V[(((size_t)b * SS + jn0 + j) * NKV + kh) * VD + d];
    }
    __syncthreads();

    const int w = tid >> 5, lane = tid & 31;
    float* pw = probs + w * 160;

    for (int p = w; p < 128; p += 8) {
        const int ql = p & 15, g = p >> 4;
        const int s  = qs0 + ql;
        const int h  = kh * 8 + g;
        const float* q = Q + (((size_t)b * SS + s) * NH + h) * HD;

        float dots[5] = {0.f, 0.f, 0.f, 0.f, 0.f};
        for (int d = 0; d < HD; d += 4) {
            float4 q4 = *(const float4*)(q + d);
#pragma unroll
            for (int u = 0; u < 4; u++) {
                float qd = (&q4.x)[u];
                const float* kr = ks + (d + u) * KP + lane;
#pragma unroll
                for (int kk = 0; kk < 5; kk++)
                    dots[kk] += qd * kr[kk * 32];
            }
        }

        float m = -1e30f;
        float sc[5];
#pragma unroll
        for (int kk = 0; kk < 5; kk++) {
            int j  = lane + kk * 32;
            int jg = jn0 + j;
            bool valid = (j < nk) && (jg <= s) && (s - jg < WIN);
            sc[kk] = valid ? dots[kk] * SCALE : -1e30f;
            m = fmaxf(m, sc[kk]);
        }
#pragma unroll
        for (int off = 16; off > 0; off >>= 1)
            m = fmaxf(m, __shfl_xor_sync(0xffffffffu, m, off));
        const float snk = sinks[h];
        m = fmaxf(m, snk);

        float ssum = 0.f;
        float pv[5];
#pragma unroll
        for (int kk = 0; kk < 5; kk++) { pv[kk] = expf(sc[kk] - m); ssum += pv[kk]; }
#pragma unroll
        for (int off = 16; off > 0; off >>= 1)
            ssum += __shfl_xor_sync(0xffffffffu, ssum, off);
        ssum += expf(snk - m);
        const float inv = 1.f / ssum;

#pragma unroll
        for (int kk = 0; kk < 5; kk++)
            pw[lane + kk * 32] = pv[kk] * inv;
        __syncwarp();

        float4 acc4 = make_float4(0.f, 0.f, 0.f, 0.f);
        const int d0 = lane * 4;
        for (int j = 0; j < nk; j++) {
            float pj  = pw[j];
            float4 v4 = *(const float4*)(vs + j * VD + d0);
            acc4.x += pj * v4.x; acc4.y += pj * v4.y;
            acc4.z += pj * v4.z; acc4.w += pj * v4.w;
        }
        __half* op = O + (((size_t)b * SS + s) * NH + h) * VD + d0;
        *(__half2*)op       = __floats2half2_rn(acc4.x, acc4.y);
        *(__half2*)(op + 2) = __floats2half2_rn(acc4.z, acc4.w);
        __syncwarp();
    }
}

// ---------------------------------------------------------------------------
// Launcher
// ---------------------------------------------------------------------------
extern "C" void kernel_launch(void* const* d_in, const int* in_sizes, int n_in,
                              void* d_out, int out_size)
{
    const float* H     = (const float*)d_in[0];
    const float* cosp  = (const float*)d_in[1];
    const float* sinp  = (const float*)d_in[2];
    const float* Wq    = (const float*)d_in[3];
    const float* Wk    = (const float*)d_in[4];
    const float* Wv    = (const float*)d_in[5];
    const float* Wo    = (const float*)d_in[6];
    const float* sinks = (const float*)d_in[7];
    float* out = (float*)d_out;

    float *Qb, *Kb, *Vb;
    __half *Hh, *Wqh, *Wkh, *Wvh, *Woh, *AOh;
    cudaGetSymbolAddress((void**)&Qb,  g_Q);
    cudaGetSymbolAddress((void**)&Kb,  g_K);
    cudaGetSymbolAddress((void**)&Vb,  g_V);
    cudaGetSymbolAddress((void**)&Hh,  g_Hh);
    cudaGetSymbolAddress((void**)&Wqh, g_Wqh);
    cudaGetSymbolAddress((void**)&Wkh, g_Wkh);
    cudaGetSymbolAddress((void**)&Wvh, g_Wvh);
    cudaGetSymbolAddress((void**)&Woh, g_Woh);
    cudaGetSymbolAddress((void**)&AOh, g_AOh);

    const int M = BB * SS;   // 2048
    static bool attr_set = false;
    if (!attr_set) {
        cudaFuncSetAttribute(gemm_qkv,
                             cudaFuncAttributeMaxDynamicSharedMemorySize, GEMM_SMEM);
        cudaFuncSetAttribute(gemm_gen,
                             cudaFuncAttributeMaxDynamicSharedMemorySize, GEMM_SMEM);
        attr_set = true;
    }

    // fp32 -> fp16 operand conversion (16 elems/thread)
    f32_to_f16<<<(M * HID)   / 4096, 256>>>(H,  Hh);
    f32_to_f16<<<(HID * NQ)  / 4096, 256>>>(Wq, Wqh);
    f32_to_f16<<<(HID * NK)  / 4096, 256>>>(Wk, Wkh);
    f32_to_f16<<<(HID * NV)  / 4096, 256>>>(Wv, Wvh);
    f32_to_f16<<<(NO * HID)  / 4096, 256>>>(Wo, Woh);

    // fused QKV projection (CTA 128x256)
    gemm_qkv<<<dim3((NQ + NK + NV) / 256, M / 128), 256, GEMM_SMEM>>>(
        Hh, Wqh, Wkh, Wvh, Qb, Kb, Vb);

    // partial RoPE
    rope_kernel<<<(M * NH  * 32) / 256, 256>>>(Qb, cosp, sinp, NH);
    rope_kernel<<<(M * NKV * 32) / 256, 256>>>(Kb, cosp, sinp, NKV);

    // attention -> fp16 AO
    const int att_smem = (HD * KP + 144 * VD + 8 * 160) * (int)sizeof(float);
    cudaFuncSetAttribute(attn_kernel,
                         cudaFuncAttributeMaxDynamicSharedMemorySize, att_smem);
    attn_kernel<<<dim3(SS / QT, NKV, BB), 256, att_smem>>>(Qb, Kb, Vb, sinks, AOh);

    // output projection
    gemm_gen<<<dim3(HID / 256, M / 128), 256, GEMM_SMEM>>>(
        AOh, Woh, out, NO, HID, NO);
}

// round 11
// speedup vs baseline: 1.3722x; 1.3722x over previous
#include <cuda_runtime.h>
#include <cuda_fp16.h>
#include <cuda_bf16.h>
#include <cstdint>

// ---------------------------------------------------------------------------
// Problem constants
// ---------------------------------------------------------------------------
#define BB    2
#define SS    1024
#define HID   4096
#define NH    64
#define NKV   8
#define HD    192
#define VD    128
#define ROT   64
#define WIN   128
#define QT    16
#define KP    161
#define SCALE 0.07216878364870323f   // 192^-0.5

#define NQ (NH * HD)     // 12288
#define NK (NKV * HD)    // 1536
#define NV (NKV * VD)    // 1024
#define NO (NH * VD)     // 8192

// ---------------------------------------------------------------------------
// Scratch (device globals; no allocations allowed)
// ---------------------------------------------------------------------------
__device__ __half g_Qh [(size_t)BB * SS * NQ];    // fp16 QKV (RoPE'd in place)
__device__ __half g_Kh [(size_t)BB * SS * NK];
__device__ __half g_Vh [(size_t)BB * SS * NV];
__device__ __half g_Hh [(size_t)BB * SS * HID];   // fp16 operand copies
__device__ __half g_Wqh[(size_t)HID * NQ];
__device__ __half g_Wkh[(size_t)HID * NK];
__device__ __half g_Wvh[(size_t)HID * NV];
__device__ __half g_Woh[(size_t)NO * HID];
__device__ __half g_AOh[(size_t)BB * SS * NO];    // attention output (fp16)

// ---------------------------------------------------------------------------
// Helpers
// ---------------------------------------------------------------------------
__device__ __forceinline__ uint32_t smem_u32(const void* p) {
    return (uint32_t)__cvta_generic_to_shared(p);
}

#define CP_ASYNC16(dst, src) \
    asm volatile("cp.async.cg.shared.global [%0], [%1], 16;" \
                 :: "r"(dst), "l"(src))
#define CP_COMMIT() asm volatile("cp.async.commit_group;" ::: "memory")
#define CP_WAIT1()  asm volatile("cp.async.wait_group 1;"  ::: "memory")

// ---------------------------------------------------------------------------
// fp16 mma.sync GEMM core: C(MxN) = A(MxK fp16) * B(KxN fp16), row-major.
// CTA tile 128x128, K-chunk 64, 3-stage cp.async pipeline, 2 CTAs/SM.
// 8 warps (2x4), warp tile 64x32, mma m16n8k16. C = fp16 or fp32.
// ---------------------------------------------------------------------------
#define APITCH_B  144           // bytes per A smem row (64 fp16 + 16B pad)
#define BPITCH_B  272           // bytes per B smem row (128 fp16 + 16B pad)
#define A_BYTES   (128 * APITCH_B)          // 18432
#define STAGE_B   (A_BYTES + 64 * BPITCH_B) // 35840
#define GEMM_SMEM (3 * STAGE_B)             // 107520

template <typename CT>
__device__ __forceinline__ void gemm_core(
    const __half* __restrict__ Ag, int lda,
    const __half* __restrict__ Bg, int ldb,
    CT* __restrict__ Cg, int ldc, int Kdim)
{
    extern __shared__ char smraw[];
    const uint32_t sb0 = smem_u32(smraw);
    const int tid = threadIdx.x, lane = tid & 31, warp = tid >> 5;
    const int wm = warp & 1, wn = warp >> 1;

    // fragment smem offsets (stage-relative)
    uint32_t aoff[4], boff[2];
#pragma unroll
    for (int mt = 0; mt < 4; mt++)
        aoff[mt] = (uint32_t)(wm * 64 + mt * 16 + (lane & 15)) * APITCH_B
                 + (uint32_t)(lane >> 4) * 16;
#pragma unroll
    for (int n2 = 0; n2 < 2; n2++)
        boff[n2] = A_BYTES + (uint32_t)(lane & 15) * BPITCH_B
                 + (uint32_t)(wn * 32 + n2 * 16) * 2
                 + (uint32_t)(lane >> 4) * 16;

    float acc[4][4][4];
#pragma unroll
    for (int mt = 0; mt < 4; mt++)
#pragma unroll
        for (int nt = 0; nt < 4; nt++)
#pragma unroll
            for (int r = 0; r < 4; r++) acc[mt][nt][r] = 0.f;

    const int KT = Kdim >> 6;

    // copy indices: A 4 chunks/thread, B 4 chunks/thread (16B each)
    const int am = tid >> 3, ac16 = tid & 7;       // A: rows 0..127 x 8 cols
    const int bk = tid >> 4, bc16 = tid & 15;      // B: rows (0..15)+16i x 16 cols
#define ISSUE_COPY(ktc, s) do {                                                \
        const int _k0 = (ktc) * 64;                                            \
        const uint32_t _sa = sb0 + (s) * STAGE_B;                              \
        _Pragma("unroll")                                                      \
        for (int _i = 0; _i < 4; _i++)                                         \
            CP_ASYNC16(_sa + (am + _i * 32) * APITCH_B + ac16 * 16,            \
                       Ag + (size_t)(am + _i * 32) * lda + _k0 + ac16 * 8);    \
        _Pragma("unroll")                                                      \
        for (int _i = 0; _i < 4; _i++)                                         \
            CP_ASYNC16(_sa + A_BYTES + (bk + _i * 16) * BPITCH_B + bc16 * 16,  \
                       Bg + (size_t)(_k0 + bk + _i * 16) * ldb + bc16 * 8);    \
    } while (0)

#pragma unroll
    for (int p = 0; p < 2; p++) { ISSUE_COPY(p, p); CP_COMMIT(); }

    int slot = 0;
    for (int kt = 0; kt < KT; kt++) {
        CP_WAIT1();
        __syncthreads();
        const uint32_t sa = sb0 + slot * STAGE_B;

#pragma unroll
        for (int kk = 0; kk < 4; kk++) {
            uint32_t a[4][4], b[2][4];
#pragma unroll
            for (int mt = 0; mt < 4; mt++)
                asm volatile(
                    "ldmatrix.sync.aligned.m8n8.x4.shared.b16 {%0,%1,%2,%3}, [%4];"
                    : "=r"(a[mt][0]), "=r"(a[mt][1]), "=r"(a[mt][2]), "=r"(a[mt][3])
                    : "r"(sa + aoff[mt] + kk * 32));
#pragma unroll
            for (int n2 = 0; n2 < 2; n2++)
                asm volatile(
                    "ldmatrix.sync.aligned.m8n8.x4.trans.shared.b16 {%0,%1,%2,%3}, [%4];"
                    : "=r"(b[n2][0]), "=r"(b[n2][1]), "=r"(b[n2][2]), "=r"(b[n2][3])
                    : "r"(sa + boff[n2] + kk * (16 * BPITCH_B)));
#pragma unroll
            for (int mt = 0; mt < 4; mt++)
#pragma unroll
                for (int nt = 0; nt < 4; nt++)
                    asm volatile(
                        "mma.sync.aligned.m16n8k16.row.col.f32.f16.f16.f32 "
                        "{%0,%1,%2,%3}, {%4,%5,%6,%7}, {%8,%9}, {%0,%1,%2,%3};"
                        : "+f"(acc[mt][nt][0]), "+f"(acc[mt][nt][1]),
                          "+f"(acc[mt][nt][2]), "+f"(acc[mt][nt][3])
                        : "r"(a[mt][0]), "r"(a[mt][1]), "r"(a[mt][2]), "r"(a[mt][3]),
                          "r"(b[nt >> 1][(nt & 1) * 2]), "r"(b[nt >> 1][(nt & 1) * 2 + 1]));
        }

        const int ktc = kt + 2;
        if (ktc < KT) {
            int ws = slot + 2; if (ws >= 3) ws -= 3;
            ISSUE_COPY(ktc, ws);
        }
        CP_COMMIT();
        if (++slot == 3) slot = 0;
    }
#undef ISSUE_COPY

    // epilogue
#pragma unroll
    for (int mt = 0; mt < 4; mt++) {
        const int r = wm * 64 + mt * 16 + (lane >> 2);
#pragma unroll
        for (int nt = 0; nt < 4; nt++) {
            const int cc = wn * 32 + nt * 8 + (lane & 3) * 2;
            if (sizeof(CT) == 2) {
                *(__half2*)&Cg[(size_t)r * ldc + cc] =
                    __floats2half2_rn(acc[mt][nt][0], acc[mt][nt][1]);
                *(__half2*)&Cg[(size_t)(r + 8) * ldc + cc] =
                    __floats2half2_rn(acc[mt][nt][2], acc[mt][nt][3]);
            } else {
                *(float2*)&Cg[(size_t)r * ldc + cc] =
                    make_float2(acc[mt][nt][0], acc[mt][nt][1]);
                *(float2*)&Cg[(size_t)(r + 8) * ldc + cc] =
                    make_float2(acc[mt][nt][2], acc[mt][nt][3]);
            }
        }
    }
}

// fused QKV projection: one grid over the concatenated N = 12288|1536|1024
__global__ __launch_bounds__(256, 2) void gemm_qkv(
    const __half* __restrict__ Hh,
    const __half* __restrict__ Wqh, const __half* __restrict__ Wkh,
    const __half* __restrict__ Wvh,
    __half* __restrict__ Q, __half* __restrict__ K, __half* __restrict__ V)
{
    const int col0 = blockIdx.x * 128, row0 = blockIdx.y * 128;
    const __half* Bg; __half* Cg; int ld;
    if (col0 < NQ)            { Bg = Wqh + col0;          Cg = Q + col0;          ld = NQ; }
    else if (col0 < NQ + NK)  { int c = col0 - NQ;  Bg = Wkh + c; Cg = K + c; ld = NK; }
    else                      { int c = col0 - NQ - NK; Bg = Wvh + c; Cg = V + c; ld = NV; }
    gemm_core<__half>(Hh + (size_t)row0 * HID, HID, Bg, ld,
                      Cg + (size_t)row0 * ld, ld, HID);
}

// output projection (fp32 C)
__global__ __launch_bounds__(256, 2) void gemm_gen(
    const __half* __restrict__ Ah, const __half* __restrict__ Bh,
    float* __restrict__ C, int lda, int ldb, int Kdim)
{
    const int col0 = blockIdx.x * 128, row0 = blockIdx.y * 128;
    gemm_core<float>(Ah + (size_t)row0 * lda, lda, Bh + col0, ldb,
                     C + (size_t)row0 * ldb + col0, ldb, Kdim);
}

// ---------------------------------------------------------------------------
// fp32 -> fp16 (rn) conversion, 16 elems/thread, exact grids
// ---------------------------------------------------------------------------
__global__ __launch_bounds__(256) void f32_to_f16(
    const float* __restrict__ in, __half* __restrict__ out)
{
    const size_t i = ((size_t)blockIdx.x * 256 + threadIdx.x) * 16;
    float4 a = *(const float4*)(in + i);
    float4 b = *(const float4*)(in + i + 4);
    float4 c = *(const float4*)(in + i + 8);
    float4 d = *(const float4*)(in + i + 12);
    union { __half2 h[4]; uint4 u; } cv0, cv1;
    cv0.h[0] = __floats2half2_rn(a.x, a.y);
    cv0.h[1] = __floats2half2_rn(a.z, a.w);
    cv0.h[2] = __floats2half2_rn(b.x, b.y);
    cv0.h[3] = __floats2half2_rn(b.z, b.w);
    cv1.h[0] = __floats2half2_rn(c.x, c.y);
    cv1.h[1] = __floats2half2_rn(c.z, c.w);
    cv1.h[2] = __floats2half2_rn(d.x, d.y);
    cv1.h[3] = __floats2half2_rn(d.z, d.w);
    *(uint4*)(out + i)     = cv0.u;
    *(uint4*)(out + i + 8) = cv1.u;
}

// ---------------------------------------------------------------------------
// Partial RoPE (rotate-half on first 64 dims), in place, fp16 storage.
// ---------------------------------------------------------------------------
__global__ __launch_bounds__(256) void rope_kernel(
    __half* __restrict__ X, const float* __restrict__ cosp,
    const float* __restrict__ sinp, int nheads)
{
    int idx = blockIdx.x * blockDim.x + threadIdx.x;
    int d  = idx & 31;
    int h  = (idx >> 5) % nheads;
    int bs = idx / (32 * nheads);

    __half* base = X + ((size_t)bs * nheads + h) * HD;
    float c = cosp[bs * ROT + d];
    float s = sinp[bs * ROT + d];
    float x1 = __half2float(base[d]), x2 = __half2float(base[d + 32]);
    base[d]      = __float2half_rn(x1 * c - x2 * s);
    base[d + 32] = __float2half_rn(x2 * c + x1 * s);
}

// ---------------------------------------------------------------------------
// Sliding-window attention with sink; fp16 inputs, fp32 smem/compute,
// fp16 output (GEMM operand).
// ---------------------------------------------------------------------------
__global__ __launch_bounds__(256) void attn_kernel(
    const __half* __restrict__ Q, const __half* __restrict__ K,
    const __half* __restrict__ V, const float* __restrict__ sinks,
    __half* __restrict__ O)
{
    extern __shared__ float smn[];
    float* ks    = smn;                    // [HD][KP]
    float* vs    = smn + HD * KP;          // [144][VD]
    float* probs = vs + 144 * VD;          // [8][160]

    const int qt = blockIdx.x, kh = blockIdx.y, b = blockIdx.z;
    const int qs0 = qt * QT;
    const int jn0 = max(0, qs0 - (WIN - 1));
    const int nk  = qs0 + QT - jn0;
    const int tid = threadIdx.x;

    for (int idx = tid; idx < nk * HD; idx += 256) {
        int j = idx / HD, d = idx - j * HD;
        ks[d * KP + j] =
            __half2float(K[(((size_t)b * SS + jn0 + j) * NKV + kh) * HD + d]);
    }
    for (int idx = tid; idx < nk * VD; idx += 256) {
        int j = idx >> 7, d = idx & 127;
        vs[j * VD + d] =
            __half2float(V[(((size_t)b * SS + jn0 + j) * NKV + kh) * VD + d]);
    }
    __syncthreads();

    const int w = tid >> 5, lane = tid & 31;
    float* pw = probs + w * 160;

    for (int p = w; p < 128; p += 8) {
        const int ql = p & 15, g = p >> 4;
        const int s  = qs0 + ql;
        const int h  = kh * 8 + g;
        const __half* q = Q + (((size_t)b * SS + s) * NH + h) * HD;

        float dots[5] = {0.f, 0.f, 0.f, 0.f, 0.f};
        for (int d = 0; d < HD; d += 8) {
            uint4 raw = *(const uint4*)(q + d);   // 8 halves
            const __half2* hp = (const __half2*)&raw;
#pragma unroll
            for (int u = 0; u < 4; u++) {
                float2 f = __half22float2(hp[u]);
                const float* kr0 = ks + (d + 2 * u) * KP + lane;
                const float* kr1 = kr0 + KP;
#pragma unroll
                for (int kk = 0; kk < 5; kk++) {
                    dots[kk] += f.x * kr0[kk * 32];
                    dots[kk] += f.y * kr1[kk * 32];
                }
            }
        }

        float m = -1e30f;
        float sc[5];
#pragma unroll
        for (int kk = 0; kk < 5; kk++) {
            int j  = lane + kk * 32;
            int jg = jn0 + j;
            bool valid = (j < nk) && (jg <= s) && (s - jg < WIN);
            sc[kk] = valid ? dots[kk] * SCALE : -1e30f;
            m = fmaxf(m, sc[kk]);
        }
#pragma unroll
        for (int off = 16; off > 0; off >>= 1)
            m = fmaxf(m, __shfl_xor_sync(0xffffffffu, m, off));
        const float snk = sinks[h];
        m = fmaxf(m, snk);

        float ssum = 0.f;
        float pv[5];
#pragma unroll
        for (int kk = 0; kk < 5; kk++) { pv[kk] = expf(sc[kk] - m); ssum += pv[kk]; }
#pragma unroll
        for (int off = 16; off > 0; off >>= 1)
            ssum += __shfl_xor_sync(0xffffffffu, ssum, off);
        ssum += expf(snk - m);
        const float inv = 1.f / ssum;

#pragma unroll
        for (int kk = 0; kk < 5; kk++)
            pw[lane + kk * 32] = pv[kk] * inv;
        __syncwarp();

        float4 acc4 = make_float4(0.f, 0.f, 0.f, 0.f);
        const int d0 = lane * 4;
        for (int j = 0; j < nk; j++) {
            float pj  = pw[j];
            float4 v4 = *(const float4*)(vs + j * VD + d0);
            acc4.x += pj * v4.x; acc4.y += pj * v4.y;
            acc4.z += pj * v4.z; acc4.w += pj * v4.w;
        }
        __half* op = O + (((size_t)b * SS + s) * NH + h) * VD + d0;
        *(__half2*)op       = __floats2half2_rn(acc4.x, acc4.y);
        *(__half2*)(op + 2) = __floats2half2_rn(acc4.z, acc4.w);
        __syncwarp();
    }
}

// ---------------------------------------------------------------------------
// Launcher
// ---------------------------------------------------------------------------
extern "C" void kernel_launch(void* const* d_in, const int* in_sizes, int n_in,
                              void* d_out, int out_size)
{
    const float* H     = (const float*)d_in[0];
    const float* cosp  = (const float*)d_in[1];
    const float* sinp  = (const float*)d_in[2];
    const float* Wq    = (const float*)d_in[3];
    const float* Wk    = (const float*)d_in[4];
    const float* Wv    = (const float*)d_in[5];
    const float* Wo    = (const float*)d_in[6];
    const float* sinks = (const float*)d_in[7];
    float* out = (float*)d_out;

    __half *Qh, *Kh, *Vh, *Hh, *Wqh, *Wkh, *Wvh, *Woh, *AOh;
    cudaGetSymbolAddress((void**)&Qh,  g_Qh);
    cudaGetSymbolAddress((void**)&Kh,  g_Kh);
    cudaGetSymbolAddress((void**)&Vh,  g_Vh);
    cudaGetSymbolAddress((void**)&Hh,  g_Hh);
    cudaGetSymbolAddress((void**)&Wqh, g_Wqh);
    cudaGetSymbolAddress((void**)&Wkh, g_Wkh);
    cudaGetSymbolAddress((void**)&Wvh, g_Wvh);
    cudaGetSymbolAddress((void**)&Woh, g_Woh);
    cudaGetSymbolAddress((void**)&AOh, g_AOh);

    const int M = BB * SS;   // 2048
    static bool attr_set = false;
    if (!attr_set) {
        cudaFuncSetAttribute(gemm_qkv,
                             cudaFuncAttributeMaxDynamicSharedMemorySize, GEMM_SMEM);
        cudaFuncSetAttribute(gemm_gen,
                             cudaFuncAttributeMaxDynamicSharedMemorySize, GEMM_SMEM);
        attr_set = true;
    }

    // fp32 -> fp16 operand conversion (16 elems/thread)
    f32_to_f16<<<(M * HID)   / 4096, 256>>>(H,  Hh);
    f32_to_f16<<<(HID * NQ)  / 4096, 256>>>(Wq, Wqh);
    f32_to_f16<<<(HID * NK)  / 4096, 256>>>(Wk, Wkh);
    f32_to_f16<<<(HID * NV)  / 4096, 256>>>(Wv, Wvh);
    f32_to_f16<<<(NO * HID)  / 4096, 256>>>(Wo, Woh);

    // fused QKV projection (fp16 out)
    gemm_qkv<<<dim3((NQ + NK + NV) / 128, M / 128), 256, GEMM_SMEM>>>(
        Hh, Wqh, Wkh, Wvh, Qh, Kh, Vh);

    // partial RoPE (fp16 in place)
    rope_kernel<<<(M * NH  * 32) / 256, 256>>>(Qh, cosp, sinp, NH);
    rope_kernel<<<(M * NKV * 32) / 256, 256>>>(Kh, cosp, sinp, NKV);

    // attention -> fp16 AO
    const int att_smem = (HD * KP + 144 * VD + 8 * 160) * (int)sizeof(float);
    cudaFuncSetAttribute(attn_kernel,
                         cudaFuncAttributeMaxDynamicSharedMemorySize, att_smem);
    attn_kernel<<<dim3(SS / QT, NKV, BB), 256, att_smem>>>(Qh, Kh, Vh, sinks, AOh);

    // output projection (fp32 out)
    gemm_gen<<<dim3(HID / 128, M / 128), 256, GEMM_SMEM>>>(
        AOh, Woh, out, NO, HID, NO);
}

// round 13
// speedup vs baseline: 2.5106x; 1.8296x over previous
#include <cuda_runtime.h>
#include <cuda_fp16.h>
#include <cuda_bf16.h>
#include <cstdint>

// ---------------------------------------------------------------------------
// Problem constants
// ---------------------------------------------------------------------------
#define BB    2
#define SS    1024
#define HID   4096
#define NH    64
#define NKV   8
#define HD    192
#define VD    128
#define ROT   64
#define WIN   128
#define SCALE 0.07216878364870323f   // 192^-0.5

#define NQ (NH * HD)     // 12288
#define NK (NKV * HD)    // 1536
#define NV (NKV * VD)    // 1024
#define NO (NH * VD)     // 8192

// ---------------------------------------------------------------------------
// Scratch (device globals; no allocations allowed)
// ---------------------------------------------------------------------------
__device__ __half g_Qh [(size_t)BB * SS * NQ];    // fp16 QKV (RoPE'd in place)
__device__ __half g_Kh [(size_t)BB * SS * NK];
__device__ __half g_Vh [(size_t)BB * SS * NV];
__device__ __half g_Hh [(size_t)BB * SS * HID];   // fp16 operand copies
__device__ __half g_Wqh[(size_t)HID * NQ];
__device__ __half g_Wkh[(size_t)HID * NK];
__device__ __half g_Wvh[(size_t)HID * NV];
__device__ __half g_Woh[(size_t)NO * HID];
__device__ __half g_AOh[(size_t)BB * SS * NO];    // attention output (fp16)

// ---------------------------------------------------------------------------
// Helpers
// ---------------------------------------------------------------------------
__device__ __forceinline__ uint32_t smem_u32(const void* p) {
    return (uint32_t)__cvta_generic_to_shared(p);
}

#define CP_ASYNC16(dst, src) \
    asm volatile("cp.async.cg.shared.global [%0], [%1], 16;" \
                 :: "r"(dst), "l"(src))
#define CP_COMMIT() asm volatile("cp.async.commit_group;" ::: "memory")
#define CP_WAIT1()  asm volatile("cp.async.wait_group 1;"  ::: "memory")
#define CP_WAIT0()  asm volatile("cp.async.wait_group 0;"  ::: "memory")

#define LDSM_X4(r, addr)                                                       \
    asm volatile("ldmatrix.sync.aligned.m8n8.x4.shared.b16 {%0,%1,%2,%3}, [%4];" \
        : "=r"((r)[0]), "=r"((r)[1]), "=r"((r)[2]), "=r"((r)[3]) : "r"(addr))
#define LDSM_X4T(r, addr)                                                      \
    asm volatile("ldmatrix.sync.aligned.m8n8.x4.trans.shared.b16 {%0,%1,%2,%3}, [%4];" \
        : "=r"((r)[0]), "=r"((r)[1]), "=r"((r)[2]), "=r"((r)[3]) : "r"(addr))
#define MMA16816(c, a0, a1, a2, a3, b0, b1)                                    \
    asm volatile("mma.sync.aligned.m16n8k16.row.col.f32.f16.f16.f32 "          \
        "{%0,%1,%2,%3}, {%4,%5,%6,%7}, {%8,%9}, {%0,%1,%2,%3};"                \
        : "+f"((c)[0]), "+f"((c)[1]), "+f"((c)[2]), "+f"((c)[3])               \
        : "r"(a0), "r"(a1), "r"(a2), "r"(a3), "r"(b0), "r"(b1))

// ---------------------------------------------------------------------------
// fp16 mma.sync GEMM core (unchanged from round 10 winner)
// ---------------------------------------------------------------------------
#define APITCH_B  144
#define BPITCH_B  272
#define A_BYTES   (128 * APITCH_B)          // 18432
#define STAGE_B   (A_BYTES + 64 * BPITCH_B) // 35840
#define GEMM_SMEM (3 * STAGE_B)             // 107520

template <typename CT>
__device__ __forceinline__ void gemm_core(
    const __half* __restrict__ Ag, int lda,
    const __half* __restrict__ Bg, int ldb,
    CT* __restrict__ Cg, int ldc, int Kdim)
{
    extern __shared__ char smraw[];
    const uint32_t sb0 = smem_u32(smraw);
    const int tid = threadIdx.x, lane = tid & 31, warp = tid >> 5;
    const int wm = warp & 1, wn = warp >> 1;

    uint32_t aoff[4], boff[2];
#pragma unroll
    for (int mt = 0; mt < 4; mt++)
        aoff[mt] = (uint32_t)(wm * 64 + mt * 16 + (lane & 15)) * APITCH_B
                 + (uint32_t)(lane >> 4) * 16;
#pragma unroll
    for (int n2 = 0; n2 < 2; n2++)
        boff[n2] = A_BYTES + (uint32_t)(lane & 15) * BPITCH_B
                 + (uint32_t)(wn * 32 + n2 * 16) * 2
                 + (uint32_t)(lane >> 4) * 16;

    float acc[4][4][4];
#pragma unroll
    for (int mt = 0; mt < 4; mt++)
#pragma unroll
        for (int nt = 0; nt < 4; nt++)
#pragma unroll
            for (int r = 0; r < 4; r++) acc[mt][nt][r] = 0.f;

    const int KT = Kdim >> 6;
    const int am = tid >> 3, ac16 = tid & 7;
    const int bk = tid >> 4, bc16 = tid & 15;
#define ISSUE_COPY(ktc, s) do {                                                \
        const int _k0 = (ktc) * 64;                                            \
        const uint32_t _sa = sb0 + (s) * STAGE_B;                              \
        _Pragma("unroll")                                                      \
        for (int _i = 0; _i < 4; _i++)                                         \
            CP_ASYNC16(_sa + (am + _i * 32) * APITCH_B + ac16 * 16,            \
                       Ag + (size_t)(am + _i * 32) * lda + _k0 + ac16 * 8);    \
        _Pragma("unroll")                                                      \
        for (int _i = 0; _i < 4; _i++)                                         \
            CP_ASYNC16(_sa + A_BYTES + (bk + _i * 16) * BPITCH_B + bc16 * 16,  \
                       Bg + (size_t)(_k0 + bk + _i * 16) * ldb + bc16 * 8);    \
    } while (0)

#pragma unroll
    for (int p = 0; p < 2; p++) { ISSUE_COPY(p, p); CP_COMMIT(); }

    int slot = 0;
    for (int kt = 0; kt < KT; kt++) {
        CP_WAIT1();
        __syncthreads();
        const uint32_t sa = sb0 + slot * STAGE_B;

#pragma unroll
        for (int kk = 0; kk < 4; kk++) {
            uint32_t a[4][4], b[2][4];
#pragma unroll
            for (int mt = 0; mt < 4; mt++)
                LDSM_X4(a[mt], sa + aoff[mt] + kk * 32);
#pragma unroll
            for (int n2 = 0; n2 < 2; n2++)
                LDSM_X4T(b[n2], sa + boff[n2] + kk * (16 * BPITCH_B));
#pragma unroll
            for (int mt = 0; mt < 4; mt++)
#pragma unroll
                for (int nt = 0; nt < 4; nt++)
                    MMA16816(acc[mt][nt],
                             a[mt][0], a[mt][1], a[mt][2], a[mt][3],
                             b[nt >> 1][(nt & 1) * 2], b[nt >> 1][(nt & 1) * 2 + 1]);
        }

        const int ktc = kt + 2;
        if (ktc < KT) {
            int ws = slot + 2; if (ws >= 3) ws -= 3;
            ISSUE_COPY(ktc, ws);
        }
        CP_COMMIT();
        if (++slot == 3) slot = 0;
    }
#undef ISSUE_COPY

#pragma unroll
    for (int mt = 0; mt < 4; mt++) {
        const int r = wm * 64 + mt * 16 + (lane >> 2);
#pragma unroll
        for (int nt = 0; nt < 4; nt++) {
            const int cc = wn * 32 + nt * 8 + (lane & 3) * 2;
            if (sizeof(CT) == 2) {
                *(__half2*)&Cg[(size_t)r * ldc + cc] =
                    __floats2half2_rn(acc[mt][nt][0], acc[mt][nt][1]);
                *(__half2*)&Cg[(size_t)(r + 8) * ldc + cc] =
                    __floats2half2_rn(acc[mt][nt][2], acc[mt][nt][3]);
            } else {
                *(float2*)&Cg[(size_t)r * ldc + cc] =
                    make_float2(acc[mt][nt][0], acc[mt][nt][1]);
                *(float2*)&Cg[(size_t)(r + 8) * ldc + cc] =
                    make_float2(acc[mt][nt][2], acc[mt][nt][3]);
            }
        }
    }
}

__global__ __launch_bounds__(256, 2) void gemm_qkv(
    const __half* __restrict__ Hh,
    const __half* __restrict__ Wqh, const __half* __restrict__ Wkh,
    const __half* __restrict__ Wvh,
    __half* __restrict__ Q, __half* __restrict__ K, __half* __restrict__ V)
{
    const int col0 = blockIdx.x * 128, row0 = blockIdx.y * 128;
    const __half* Bg; __half* Cg; int ld;
    if (col0 < NQ)            { Bg = Wqh + col0;          Cg = Q + col0;          ld = NQ; }
    else if (col0 < NQ + NK)  { int c = col0 - NQ;  Bg = Wkh + c; Cg = K + c; ld = NK; }
    else                      { int c = col0 - NQ - NK; Bg = Wvh + c; Cg = V + c; ld = NV; }
    gemm_core<__half>(Hh + (size_t)row0 * HID, HID, Bg, ld,
                      Cg + (size_t)row0 * ld, ld, HID);
}

__global__ __launch_bounds__(256, 2) void gemm_gen(
    const __half* __restrict__ Ah, const __half* __restrict__ Bh,
    float* __restrict__ C, int lda, int ldb, int Kdim)
{
    const int col0 = blockIdx.x * 128, row0 = blockIdx.y * 128;
    gemm_core<float>(Ah + (size_t)row0 * lda, lda, Bh + col0, ldb,
                     C + (size_t)row0 * ldb + col0, ldb, Kdim);
}

// ---------------------------------------------------------------------------
// fp32 -> fp16 (rn) conversion, 32 elems/thread
// ---------------------------------------------------------------------------
__global__ __launch_bounds__(256) void f32_to_f16(
    const float* __restrict__ in, __half* __restrict__ out)
{
    const size_t i = ((size_t)blockIdx.x * 256 + threadIdx.x) * 32;
#pragma unroll
    for (int u = 0; u < 4; u++) {
        float4 a = *(const float4*)(in + i + u * 8);
        float4 b = *(const float4*)(in + i + u * 8 + 4);
        union { __half2 h[4]; uint4 v; } cv;
        cv.h[0] = __floats2half2_rn(a.x, a.y);
        cv.h[1] = __floats2half2_rn(a.z, a.w);
        cv.h[2] = __floats2half2_rn(b.x, b.y);
        cv.h[3] = __floats2half2_rn(b.z, b.w);
        *(uint4*)(out + i + u * 8) = cv.v;
    }
}

// ---------------------------------------------------------------------------
// Partial RoPE (rotate-half on first 64 dims), in place, fp16 storage.
// ---------------------------------------------------------------------------
__global__ __launch_bounds__(256) void rope_kernel(
    __half* __restrict__ X, const float* __restrict__ cosp,
    const float* __restrict__ sinp, int nheads)
{
    int idx = blockIdx.x * blockDim.x + threadIdx.x;
    int d  = idx & 31;
    int h  = (idx >> 5) % nheads;
    int bs = idx / (32 * nheads);

    __half* base = X + ((size_t)bs * nheads + h) * HD;
    float c = cosp[bs * ROT + d];
    float s = sinp[bs * ROT + d];
    float x1 = __half2float(base[d]), x2 = __half2float(base[d + 32]);
    base[d]      = __float2half_rn(x1 * c - x2 * s);
    base[d + 32] = __float2half_rn(x2 * c + x1 * s);
}

// ---------------------------------------------------------------------------
// Tensor-core sliding-window attention with sink.
// Block = (16-query tile, kv-head, batch); 8 warps = 8 q-heads sharing K/V.
// S[128rows=head*16+q][160keys] = Q @ K^T via mma (K non-trans ldmatrix),
// register softmax, P fp16 in regs, O = P @ V via mma (V trans ldmatrix).
// ---------------------------------------------------------------------------
#define QPB 400                       // Q/K smem pitch bytes (192h + pad)
#define VPB 272                       // V smem pitch bytes (128h + pad)
#define SQ_OFF 0
#define SK_OFF (128 * QPB)            // 51200
#define SV_OFF (SK_OFF + 160 * QPB)   // 115200
#define ATT_SMEM (SV_OFF + 160 * VPB) // 158720

__global__ __launch_bounds__(256, 1) void attn_kernel(
    const __half* __restrict__ Q, const __half* __restrict__ K,
    const __half* __restrict__ V, const float* __restrict__ sinks,
    __half* __restrict__ O)
{
    extern __shared__ char smatt[];
    const uint32_t sb = smem_u32(smatt);
    const int qt = blockIdx.x, kh = blockIdx.y, b = blockIdx.z;
    const int qs0 = qt * 16;
    const int jn0 = max(0, qs0 - (WIN - 1));
    const int tid = threadIdx.x, lane = tid & 31, w = tid >> 5;

    // ---- loads: Q 128x192, K 160x192, V 160x128 (fp16, cp.async) ----
#pragma unroll
    for (int i = 0; i < 12; i++) {               // Q: 3072 16B chunks
        int c = tid + 256 * i;
        int r = c / 24, cc = c - r * 24;         // r = g*16+ql
        const __half* src = Q + (((size_t)b * SS + qs0 + (r & 15)) * NH
                                 + kh * 8 + (r >> 4)) * HD + cc * 8;
        CP_ASYNC16(sb + SQ_OFF + r * QPB + cc * 16, src);
    }
#pragma unroll
    for (int i = 0; i < 15; i++) {               // K: 3840 chunks
        int c = tid + 256 * i;
        int j = c / 24, cc = c - j * 24;
        int sj = min(jn0 + j, SS - 1);
        const __half* src = K + (((size_t)b * SS + sj) * NKV + kh) * HD + cc * 8;
        CP_ASYNC16(sb + SK_OFF + j * QPB + cc * 16, src);
    }
#pragma unroll
    for (int i = 0; i < 10; i++) {               // V: 2560 chunks
        int c = tid + 256 * i;
        int j = c >> 4, cc = c & 15;
        int sj = min(jn0 + j, SS - 1);
        const __half* src = V + (((size_t)b * SS + sj) * NKV + kh) * VD + cc * 8;
        CP_ASYNC16(sb + SV_OFF + j * VPB + cc * 16, src);
    }
    CP_COMMIT();
    CP_WAIT0();
    __syncthreads();

    // ---- score MMA: per warp S[16][160], rows = head w, queries 0..15 ----
    float sacc[20][4];
#pragma unroll
    for (int nt = 0; nt < 20; nt++)
#pragma unroll
        for (int r = 0; r < 4; r++) sacc[nt][r] = 0.f;

    const uint32_t qbase = sb + SQ_OFF + (w * 16 + (lane & 15)) * QPB
                         + (lane >> 4) * 16;
    // non-trans K b-frags: rows = key j, cols = d
    const uint32_t kbase = sb + SK_OFF + ((lane & 7) + ((lane >> 1) & 8)) * QPB
                         + (lane & 8) * 2;
#pragma unroll
    for (int ks = 0; ks < 12; ks++) {
        uint32_t a[4];
        LDSM_X4(a, qbase + ks * 32);
#pragma unroll
        for (int t = 0; t < 10; t++) {
            uint32_t bf[4];
            LDSM_X4(bf, kbase + t * (16 * QPB) + ks * 32);
            MMA16816(sacc[2 * t],     a[0], a[1], a[2], a[3], bf[0], bf[1]);
            MMA16816(sacc[2 * t + 1], a[0], a[1], a[2], a[3], bf[2], bf[3]);
        }
    }

    // ---- register softmax (rows: r0 = lane>>2, r1 = r0+8) ----
    const int s0r = qs0 + (lane >> 2), s1r = s0r + 8;
    const float snk = sinks[kh * 8 + w];
    float m0 = snk, m1 = snk;
#pragma unroll
    for (int nt = 0; nt < 20; nt++) {
#pragma unroll
        for (int e = 0; e < 2; e++) {
            int jg = jn0 + nt * 8 + (lane & 3) * 2 + e;
            bool v0 = (jg <= s0r) && (s0r - jg < WIN);
            bool v1 = (jg <= s1r) && (s1r - jg < WIN);
            sacc[nt][e]     = v0 ? sacc[nt][e] * SCALE     : -1e30f;
            sacc[nt][e + 2] = v1 ? sacc[nt][e + 2] * SCALE : -1e30f;
            m0 = fmaxf(m0, sacc[nt][e]);
            m1 = fmaxf(m1, sacc[nt][e + 2]);
        }
    }
    m0 = fmaxf(m0, __shfl_xor_sync(0xffffffffu, m0, 1));
    m0 = fmaxf(m0, __shfl_xor_sync(0xffffffffu, m0, 2));
    m1 = fmaxf(m1, __shfl_xor_sync(0xffffffffu, m1, 1));
    m1 = fmaxf(m1, __shfl_xor_sync(0xffffffffu, m1, 2));

    float sum0 = 0.f, sum1 = 0.f;
    uint32_t p16[20][2];
#pragma unroll
    for (int nt = 0; nt < 20; nt++) {
        float p0 = expf(sacc[nt][0] - m0), p1 = expf(sacc[nt][1] - m0);
        float p2 = expf(sacc[nt][2] - m1), p3 = expf(sacc[nt][3] - m1);
        sum0 += p0 + p1; sum1 += p2 + p3;
        union { __half2 h; uint32_t u; } c01, c23;
        c01.h = __floats2half2_rn(p0, p1);
        c23.h = __floats2half2_rn(p2, p3);
        p16[nt][0] = c01.u; p16[nt][1] = c23.u;
    }
    sum0 += __shfl_xor_sync(0xffffffffu, sum0, 1);
    sum0 += __shfl_xor_sync(0xffffffffu, sum0, 2);
    sum1 += __shfl_xor_sync(0xffffffffu, sum1, 1);
    sum1 += __shfl_xor_sync(0xffffffffu, sum1, 2);
    sum0 += expf(snk - m0);
    sum1 += expf(snk - m1);
    const float inv0 = 1.f / sum0, inv1 = 1.f / sum1;

    // ---- PV MMA: O[16][128] = P[16][160] @ V[160][128] ----
    float oacc[16][4];
#pragma unroll
    for (int nt = 0; nt < 16; nt++)
#pragma unroll
        for (int r = 0; r < 4; r++) oacc[nt][r] = 0.f;

    const uint32_t vbase = sb + SV_OFF + (lane & 15) * VPB + (lane >> 4) * 16;
#pragma unroll
    for (int t = 0; t < 10; t++) {
#pragma unroll
        for (int n = 0; n < 8; n++) {
            uint32_t bf[4];
            LDSM_X4T(bf, vbase + t * (16 * VPB) + n * 32);
            MMA16816(oacc[2 * n],     p16[2 * t][0], p16[2 * t][1],
                     p16[2 * t + 1][0], p16[2 * t + 1][1], bf[0], bf[1]);
            MMA16816(oacc[2 * n + 1], p16[2 * t][0], p16[2 * t][1],
                     p16[2 * t + 1][0], p16[2 * t + 1][1], bf[2], bf[3]);
        }
    }

    // ---- epilogue: normalize, write fp16 AO ----
    const int h = kh * 8 + w;
#pragma unroll
    for (int nt = 0; nt < 16; nt++) {
        int d = nt * 8 + (lane & 3) * 2;
        __half* o0 = O + (((size_t)b * SS + s0r) * NH + h) * VD + d;
        __half* o1 = O + (((size_t)b * SS + s1r) * NH + h) * VD + d;
        *(__half2*)o0 = __floats2half2_rn(oacc[nt][0] * inv0, oacc[nt][1] * inv0);
        *(__half2*)o1 = __floats2half2_rn(oacc[nt][2] * inv1, oacc[nt][3] * inv1);
    }
}

// ---------------------------------------------------------------------------
// Launcher
// ---------------------------------------------------------------------------
extern "C" void kernel_launch(void* const* d_in, const int* in_sizes, int n_in,
                              void* d_out, int out_size)
{
    const float* H     = (const float*)d_in[0];
    const float* cosp  = (const float*)d_in[1];
    const float* sinp  = (const float*)d_in[2];
    const float* Wq    = (const float*)d_in[3];
    const float* Wk    = (const float*)d_in[4];
    const float* Wv    = (const float*)d_in[5];
    const float* Wo    = (const float*)d_in[6];
    const float* sinks = (const float*)d_in[7];
    float* out = (float*)d_out;

    __half *Qh, *Kh, *Vh, *Hh, *Wqh, *Wkh, *Wvh, *Woh, *AOh;
    cudaGetSymbolAddress((void**)&Qh,  g_Qh);
    cudaGetSymbolAddress((void**)&Kh,  g_Kh);
    cudaGetSymbolAddress((void**)&Vh,  g_Vh);
    cudaGetSymbolAddress((void**)&Hh,  g_Hh);
    cudaGetSymbolAddress((void**)&Wqh, g_Wqh);
    cudaGetSymbolAddress((void**)&Wkh, g_Wkh);
    cudaGetSymbolAddress((void**)&Wvh, g_Wvh);
    cudaGetSymbolAddress((void**)&Woh, g_Woh);
    cudaGetSymbolAddress((void**)&AOh, g_AOh);

    const int M = BB * SS;   // 2048
    static bool attr_set = false;
    if (!attr_set) {
        cudaFuncSetAttribute(gemm_qkv,
                             cudaFuncAttributeMaxDynamicSharedMemorySize, GEMM_SMEM);
        cudaFuncSetAttribute(gemm_gen,
                             cudaFuncAttributeMaxDynamicSharedMemorySize, GEMM_SMEM);
        cudaFuncSetAttribute(attn_kernel,
                             cudaFuncAttributeMaxDynamicSharedMemorySize, ATT_SMEM);
        attr_set = true;
    }

    // fp32 -> fp16 operand conversion (32 elems/thread)
    f32_to_f16<<<(M * HID)   / 8192, 256>>>(H,  Hh);
    f32_to_f16<<<(HID * NQ)  / 8192, 256>>>(Wq, Wqh);
    f32_to_f16<<<(HID * NK)  / 8192, 256>>>(Wk, Wkh);
    f32_to_f16<<<(HID * NV)  / 8192, 256>>>(Wv, Wvh);
    f32_to_f16<<<(NO * HID)  / 8192, 256>>>(Wo, Woh);

    // fused QKV projection (fp16 out)
    gemm_qkv<<<dim3((NQ + NK + NV) / 128, M / 128), 256, GEMM_SMEM>>>(
        Hh, Wqh, Wkh, Wvh, Qh, Kh, Vh);

    // partial RoPE (fp16 in place)
    rope_kernel<<<(M * NH  * 32) / 256, 256>>>(Qh, cosp, sinp, NH);
    rope_kernel<<<(M * NKV * 32) / 256, 256>>>(Kh, cosp, sinp, NKV);

    // tensor-core attention -> fp16 AO
    attn_kernel<<<dim3(SS / 16, NKV, BB), 256, ATT_SMEM>>>(Qh, Kh, Vh, sinks, AOh);

    // output projection (fp32 out)
    gemm_gen<<<dim3(HID / 128, M / 128), 256, GEMM_SMEM>>>(
        AOh, Woh, out, NO, HID, NO);
}